// round 16
// baseline (speedup 1.0000x reference)
#include <cuda_runtime.h>
#include <cuda_fp16.h>
#include <math.h>
#include <stdint.h>

#define TT 8192          // tokens = B*S
#define DD 1024          // model dim
#define EE 8             // experts
#define HH 2048          // hidden
#define NROWS (TT*2)     // top-2 routing rows
#define PADROWS (NROWS + EE*128)     // expert-padded rows (17408)
#define MAXTILES (PADROWS/128)       // 136

// GEMM tile geometry
#define BM 128
#define BN 256
#define BK 32
#define KPAD 8                        // row pad (halves): stride 40 halves = 80B
#define AST (BK + KPAD)               // 40
#define A_TILE_HL (BM * AST)          // 5120 halves
#define B_TILE_HL (BN * AST)          // 10240 halves
#define A_TILE_BYTES (A_TILE_HL*2)    // 10240
#define B_TILE_BYTES (B_TILE_HL*2)    // 20480
#define STG_BYTES (A_TILE_BYTES + B_TILE_BYTES)   // 30720
#define NSTAGE 4
#define SMEM_BYTES (NSTAGE*STG_BYTES)             // 122880

// ---------------- scratch (static device globals; no allocations) ----------
__device__ int   g_tok_e[NROWS];
__device__ float g_tok_w[NROWS];
__device__ int   g_counts[EE];
__device__ int   g_off_p[EE+1];
__device__ int   g_cnt2[EE];
__device__ int   g_row2tok[PADROWS];
__device__ float g_roww[PADROWS];
__device__ int   g_pos[NROWS];
// A tiles: [tile][ktile][128 x 40 halves]
__device__ __align__(1024) __half g_Xg[(size_t)MAXTILES * (DD/BK) * A_TILE_HL];
__device__ __align__(1024) __half g_H [(size_t)MAXTILES * (HH/BK) * A_TILE_HL];
// B tiles: [e][kt][nt][256 x 40 halves]  (n-major, k-contiguous)
__device__ __align__(1024) __half g_W1c[(size_t)EE * (DD/BK) * (HH/BN) * B_TILE_HL];
__device__ __align__(1024) __half g_W2c[(size_t)EE * (HH/BK) * (DD/BN) * B_TILE_HL];
__device__ float g_Y[(size_t)PADROWS * DD];

// ---------------- helpers ---------------------------------------------------
__device__ __forceinline__ float gelu_f(float v){
    float z = 0.7978845608028654f * (v + 0.044715f * v * v * v);
    float t; asm("tanh.approx.f32 %0, %1;" : "=f"(t) : "f"(z));
    return 0.5f * v * (1.0f + t);
}
__device__ __forceinline__ void mma16(float* c, const unsigned* a, const unsigned* b){
    asm volatile(
        "mma.sync.aligned.m16n8k16.row.col.f32.f16.f16.f32 "
        "{%0,%1,%2,%3}, {%4,%5,%6,%7}, {%8,%9}, {%0,%1,%2,%3};"
        : "+f"(c[0]), "+f"(c[1]), "+f"(c[2]), "+f"(c[3])
        : "r"(a[0]), "r"(a[1]), "r"(a[2]), "r"(a[3]), "r"(b[0]), "r"(b[1]));
}
__device__ __forceinline__ void ldsm4(unsigned* r, unsigned addr){
    asm volatile("ldmatrix.sync.aligned.m8n8.x4.shared.b16 {%0,%1,%2,%3}, [%4];"
        : "=r"(r[0]), "=r"(r[1]), "=r"(r[2]), "=r"(r[3]) : "r"(addr));
}
__device__ __forceinline__ unsigned s2u(const void* p){
    unsigned a;
    asm("{ .reg .u64 t; cvta.to.shared.u64 t, %1; cvt.u32.u64 %0, t; }" : "=r"(a) : "l"(p));
    return a;
}
__device__ __forceinline__ void mbar_init(unsigned mbar, unsigned cnt){
    asm volatile("mbarrier.init.shared.b64 [%0], %1;" :: "r"(mbar), "r"(cnt) : "memory");
}
__device__ __forceinline__ void mbar_expect(unsigned mbar, unsigned bytes){
    asm volatile("mbarrier.arrive.expect_tx.shared.b64 _, [%0], %1;" :: "r"(mbar), "r"(bytes) : "memory");
}
__device__ __forceinline__ void mbar_arrive(unsigned mbar){
    asm volatile("mbarrier.arrive.shared.b64 _, [%0];" :: "r"(mbar) : "memory");
}
__device__ __forceinline__ void mbar_wait(unsigned mbar, unsigned parity){
    asm volatile(
        "{\n\t"
        ".reg .pred P;\n\t"
        "LAB_%=:\n\t"
        "mbarrier.try_wait.parity.acquire.cta.shared::cta.b64 P, [%0], %1, 0x989680;\n\t"
        "@!P bra LAB_%=;\n\t"
        "}"
        :: "r"(mbar), "r"(parity) : "memory");
}
__device__ __forceinline__ void bulk_g2s(unsigned dst, const void* src, unsigned bytes, unsigned mbar){
    asm volatile(
        "cp.async.bulk.shared::cluster.global.mbarrier::complete_tx::bytes [%0], [%1], %2, [%3];"
        :: "r"(dst), "l"(src), "r"(bytes), "r"(mbar) : "memory");
}

// ---------------- kernel 0: zero per-launch state ---------------------------
__global__ void init_kernel(){
    if (threadIdx.x < EE) g_counts[threadIdx.x] = 0;
}

// ---------------- kernel 1: gating + top-2 routing --------------------------
__global__ void gate_kernel(const float* __restrict__ x,
                            const float* __restrict__ Wg,
                            const float* __restrict__ bg){
    __shared__ float sWg[DD*EE];
    __shared__ int scnt[EE];
    const int tid = threadIdx.x;
    if (tid < EE) scnt[tid] = 0;
    for (int i = tid; i < DD*EE/4; i += 256)
        ((float4*)sWg)[i] = ((const float4*)Wg)[i];
    __syncthreads();

    const int warp = tid >> 5, lane = tid & 31;
    for (int i = 0; i < 8; ++i){
        const int t = blockIdx.x * 64 + i * 8 + warp;
        float acc[EE];
        #pragma unroll
        for (int e = 0; e < EE; ++e) acc[e] = 0.f;
        const float* xr = x + (size_t)t * DD;
        for (int j = 0; j < DD/32; ++j){
            const int d = j * 32 + lane;
            const float xv = xr[d];
            const float4* w4 = (const float4*)(sWg + d * EE);
            float4 wa = w4[0], wb = w4[1];
            acc[0] += xv*wa.x; acc[1] += xv*wa.y; acc[2] += xv*wa.z; acc[3] += xv*wa.w;
            acc[4] += xv*wb.x; acc[5] += xv*wb.y; acc[6] += xv*wb.z; acc[7] += xv*wb.w;
        }
        #pragma unroll
        for (int off = 16; off; off >>= 1){
            #pragma unroll
            for (int e = 0; e < EE; ++e)
                acc[e] += __shfl_xor_sync(0xffffffffu, acc[e], off);
        }
        if (lane == 0){
            float l[EE];
            #pragma unroll
            for (int e = 0; e < EE; ++e) l[e] = acc[e] + bg[e];
            int e0 = 0; float l0 = l[0];
            #pragma unroll
            for (int e = 1; e < EE; ++e) if (l[e] > l0){ l0 = l[e]; e0 = e; }
            int e1 = -1; float l1 = -1e30f;
            #pragma unroll
            for (int e = 0; e < EE; ++e) if (e != e0 && l[e] > l1){ l1 = l[e]; e1 = e; }
            const float w0 = 1.0f / (1.0f + __expf(l1 - l0));
            g_tok_e[2*t] = e0;  g_tok_e[2*t+1] = e1;
            g_tok_w[2*t] = w0;  g_tok_w[2*t+1] = 1.0f - w0;
            atomicAdd(&scnt[e0], 1); atomicAdd(&scnt[e1], 1);
        }
    }
    __syncthreads();
    if (tid < EE) atomicAdd(&g_counts[tid], scnt[tid]);
}

// ---------------- kernel 2: padded exclusive scan ----------------------------
__global__ void scan_kernel(){
    if (threadIdx.x == 0){
        int o = 0;
        #pragma unroll
        for (int e = 0; e < EE; ++e){
            g_off_p[e] = o;
            o += ((g_counts[e] + 127) >> 7) << 7;
        }
        g_off_p[EE] = o;
    }
    if (threadIdx.x < EE) g_cnt2[threadIdx.x] = 0;
}

// ---------------- kernel 3: scatter tokens into expert-grouped rows ---------
__global__ void scatter_kernel(){
    __shared__ int sc[EE], sbase[EE];
    const int tid = threadIdx.x;
    if (tid < EE) sc[tid] = 0;
    __syncthreads();
    const int t = blockIdx.x * 256 + tid;
    const int e0 = g_tok_e[2*t], e1 = g_tok_e[2*t+1];
    const int s0 = atomicAdd(&sc[e0], 1);
    const int s1 = atomicAdd(&sc[e1], 1);
    __syncthreads();
    if (tid < EE) sbase[tid] = atomicAdd(&g_cnt2[tid], sc[tid]);
    __syncthreads();
    const int r0 = g_off_p[e0] + sbase[e0] + s0;
    const int r1 = g_off_p[e1] + sbase[e1] + s1;
    g_row2tok[r0] = t; g_roww[r0] = g_tok_w[2*t];   g_pos[2*t]   = r0;
    g_row2tok[r1] = t; g_roww[r1] = g_tok_w[2*t+1]; g_pos[2*t+1] = r1;
}

// ---------------- kernel 4: mark padding rows --------------------------------
__global__ void padfill_kernel(){
    const int e = blockIdx.x;
    const int cnt = g_counts[e];
    const int pcnt = ((cnt + 127) >> 7) << 7;
    for (int i = cnt + threadIdx.x; i < pcnt; i += 128)
        g_row2tok[g_off_p[e] + i] = -1;
}

// ---------------- kernel 5: gather x into padded fp16 A tiles ---------------
__global__ void gather_kernel(const float* __restrict__ x){
    const int pr = blockIdx.x;
    if (pr >= g_off_p[EE]) return;
    const int tok = g_row2tok[pr];
    const int tile = pr >> 7, rl = pr & 127;
    const int j = threadIdx.x;                 // 0..255
    const int kt = j >> 3, kc = j & 7;         // ktile, 4-half chunk
    float4 v = make_float4(0.f, 0.f, 0.f, 0.f);
    if (tok >= 0) v = *(const float4*)(x + (size_t)tok * DD + kt * BK + kc * 4);
    __half2 h0 = __floats2half2_rn(v.x, v.y);
    __half2 h1 = __floats2half2_rn(v.z, v.w);
    __half* dt = g_Xg + ((size_t)tile * (DD/BK) + kt) * A_TILE_HL + rl * AST + kc * 4;
    *(__half2*)(dt)     = h0;
    *(__half2*)(dt + 2) = h1;
}

// ---------------- kernel 6: weights -> padded fp16 B tiles (n-major) --------
template<int KT, int NT>
__global__ void convw_kernel(const float* __restrict__ W, __half* __restrict__ dst){
    __shared__ float sw[32][257];
    const int t  = blockIdx.x;
    const int nt = t % NT;
    const int kt = (t / NT) % KT;
    const int e  = t / (NT * KT);
    const int ND = NT * BN;
    const float* src = W + (((size_t)e * KT + kt) * 32) * ND + nt * BN;
    for (int i = threadIdx.x; i < 32*64; i += 256){
        const int k = i >> 6, c = i & 63;
        const float4 v = *(const float4*)(src + (size_t)k * ND + c * 4);
        sw[k][c*4+0] = v.x; sw[k][c*4+1] = v.y; sw[k][c*4+2] = v.z; sw[k][c*4+3] = v.w;
    }
    __syncthreads();
    __half* dt = dst + (size_t)t * B_TILE_HL;
    for (int i = threadIdx.x; i < 2048; i += 256){
        const int n = i >> 3, kc = i & 7;
        __half2 h0 = __floats2half2_rn(sw[kc*4+0][n], sw[kc*4+1][n]);
        __half2 h1 = __floats2half2_rn(sw[kc*4+2][n], sw[kc*4+3][n]);
        __half* o = dt + n * AST + kc * 4;
        *(__half2*)(o)     = h0;
        *(__half2*)(o + 2) = h1;
    }
}

// ---------------- FP16 tensor-core grouped GEMM ------------------------------
// 16 warps (2x8), warp tile 64x32, per-kk ldmatrix, mbarrier ring (no CTA sync).
// FIRST=true : g_H tiles = fp16(gelu( g_Xg @ W1c + b1 )),  KT=32, NT=8
// FIRST=false: g_Y rows  =           g_H  @ W2c + b2,      KT=64, NT=4
template<int KT, int NT, bool FIRST>
__global__ __launch_bounds__(512, 1)
void gemm_kernel(const __half* __restrict__ Bw, const float* __restrict__ bias){
    extern __shared__ __half smh[];
    __shared__ __align__(8) unsigned long long s_bar[2*NSTAGE];

    const int e   = blockIdx.y >> 6;
    const int mt  = blockIdx.y & 63;
    const int cnt = g_counts[e];
    if (mt * BM >= cnt) return;
    const int tile = (g_off_p[e] >> 7) + mt;
    const int nt   = blockIdx.x;
    const int tid  = threadIdx.x;
    const int lane = tid & 31, wid = tid >> 5;
    const int wm = wid >> 3, wn = wid & 7;      // 2x8 warp grid, 64x32 tiles

    const __half* Asrc = FIRST ? g_Xg : g_H;
    const unsigned sb    = s2u(smh);
    const unsigned FULLB = s2u(s_bar), EMPTYB = FULLB + 8*NSTAGE;

    if (tid == 0){
        #pragma unroll
        for (int s = 0; s < NSTAGE; ++s){ mbar_init(FULLB + 8*s, 1); mbar_init(EMPTYB + 8*s, 16); }
    }
    __syncthreads();

    if (tid == 0){
        #pragma unroll
        for (int s = 0; s < NSTAGE; ++s){
            mbar_expect(FULLB + 8*s, STG_BYTES);
            bulk_g2s(sb + s*STG_BYTES,
                     Asrc + ((size_t)tile*KT + s)*A_TILE_HL, A_TILE_BYTES, FULLB + 8*s);
            bulk_g2s(sb + s*STG_BYTES + A_TILE_BYTES,
                     Bw + (((size_t)e*KT + s)*NT + nt)*B_TILE_HL, B_TILE_BYTES, FULLB + 8*s);
        }
    }

    float c[4][4][4];
    #pragma unroll
    for (int i = 0; i < 4; ++i)
        #pragma unroll
        for (int j = 0; j < 4; ++j)
            #pragma unroll
            for (int q = 0; q < 4; ++q) c[i][j][q] = 0.f;

    // ldmatrix lane addressing (half offsets within tiles, x4 form)
    const int aOff = (wm*64 + (lane & 15))*AST + (lane >> 4)*8;                // + am*16*AST + kk*16
    const int bOff = (wn*32 + (lane & 7) + ((lane >> 4) << 3))*AST + ((lane >> 3) & 1)*8;  // + bj*16*AST + kk*16

    for (int kt = 0; kt < KT; ++kt){
        const int s = kt & (NSTAGE-1);
        const unsigned ph = (kt >> 2) & 1;
        mbar_wait(FULLB + 8*s, ph);
        const unsigned As = sb + s*STG_BYTES;
        const unsigned Bs = As + A_TILE_BYTES;

        #pragma unroll
        for (int kk = 0; kk < 2; ++kk){
            unsigned a[4][4], b[2][4];
            #pragma unroll
            for (int am = 0; am < 4; ++am)
                ldsm4(a[am], As + 2*(aOff + am*16*AST + kk*16));
            #pragma unroll
            for (int bj = 0; bj < 2; ++bj)
                ldsm4(b[bj], Bs + 2*(bOff + bj*16*AST + kk*16));
            if (kk == 1){
                __syncwarp();
                if (lane == 0) mbar_arrive(EMPTYB + 8*s);
            }
            #pragma unroll
            for (int am = 0; am < 4; ++am)
                #pragma unroll
                for (int bj = 0; bj < 2; ++bj){
                    mma16(c[am][2*bj  ], a[am], &b[bj][0]);
                    mma16(c[am][2*bj+1], a[am], &b[bj][2]);
                }
        }

        if (tid == 0 && kt + NSTAGE < KT){
            mbar_wait(EMPTYB + 8*s, ph);
            mbar_expect(FULLB + 8*s, STG_BYTES);
            bulk_g2s(sb + s*STG_BYTES,
                     Asrc + ((size_t)tile*KT + kt + NSTAGE)*A_TILE_HL, A_TILE_BYTES, FULLB + 8*s);
            bulk_g2s(sb + s*STG_BYTES + A_TILE_BYTES,
                     Bw + (((size_t)e*KT + kt + NSTAGE)*NT + nt)*B_TILE_HL, B_TILE_BYTES, FULLB + 8*s);
        }
    }

    // ---- epilogue: +bias [, gelu], store ----
    const int ND = NT * BN;
    const int g = lane >> 2, tg = lane & 3;
    #pragma unroll
    for (int am = 0; am < 4; ++am){
        #pragma unroll
        for (int bn = 0; bn < 4; ++bn){
            const int lc = wn*32 + bn*8 + 2*tg;
            const int gc = nt*BN + lc;
            const float bb0 = bias[e*ND + gc];
            const float bb1 = bias[e*ND + gc + 1];
            #pragma unroll
            for (int h = 0; h < 2; ++h){
                const int r = wm*64 + am*16 + g + h*8;
                float v0 = c[am][bn][h*2+0] + bb0;
                float v1 = c[am][bn][h*2+1] + bb1;
                if (FIRST){
                    __half* dt = g_H + ((size_t)tile*(HH/BK) + (gc >> 5))*A_TILE_HL
                               + r*AST + (gc & 31);
                    *(__half2*)dt = __floats2half2_rn(gelu_f(v0), gelu_f(v1));
                } else {
                    float* dt = g_Y + ((size_t)(tile*BM + r))*DD + gc;
                    *(float2*)dt = make_float2(v0, v1);
                }
            }
        }
    }
}

// ---------------- kernel 9: weighted combine (no atomics) -------------------
__global__ void combine_kernel(float* __restrict__ out){
    const int t = blockIdx.x, i = threadIdx.x;
    const int r0 = g_pos[2*t], r1 = g_pos[2*t+1];
    const float w0 = g_roww[r0], w1 = g_roww[r1];
    const float4 a = ((const float4*)(g_Y + (size_t)r0 * DD))[i];
    const float4 b = ((const float4*)(g_Y + (size_t)r1 * DD))[i];
    float4 r;
    r.x = w0*a.x + w1*b.x; r.y = w0*a.y + w1*b.y;
    r.z = w0*a.z + w1*b.z; r.w = w0*a.w + w1*b.w;
    ((float4*)(out + (size_t)t * DD))[i] = r;
}

// ---------------- launch -----------------------------------------------------
extern "C" void kernel_launch(void* const* d_in, const int* in_sizes, int n_in,
                              void* d_out, int out_size){
    // input order: x, top_k(scalar), Wg, bg, W1, b1, W2, b2 (robust to dropped scalar)
    const int sh = (n_in >= 8) ? 0 : -1;
    const float* x  = (const float*)d_in[0];
    const float* Wg = (const float*)d_in[2 + sh];
    const float* bg = (const float*)d_in[3 + sh];
    const float* W1 = (const float*)d_in[4 + sh];
    const float* b1 = (const float*)d_in[5 + sh];
    const float* W2 = (const float*)d_in[6 + sh];
    const float* b2 = (const float*)d_in[7 + sh];
    float* out = (float*)d_out;

    __half* w1c; cudaGetSymbolAddress((void**)&w1c, g_W1c);
    __half* w2c; cudaGetSymbolAddress((void**)&w2c, g_W2c);

    cudaFuncSetAttribute(gemm_kernel<DD/BK, HH/BN, true >,
                         cudaFuncAttributeMaxDynamicSharedMemorySize, SMEM_BYTES);
    cudaFuncSetAttribute(gemm_kernel<HH/BK, DD/BN, false>,
                         cudaFuncAttributeMaxDynamicSharedMemorySize, SMEM_BYTES);

    init_kernel<<<1, 32>>>();
    gate_kernel<<<128, 256>>>(x, Wg, bg);
    scan_kernel<<<1, 32>>>();
    scatter_kernel<<<TT/256, 256>>>();
    padfill_kernel<<<EE, 128>>>();
    gather_kernel<<<PADROWS, 256>>>(x);
    convw_kernel<DD/BK, HH/BN><<<EE*(DD/BK)*(HH/BN), 256>>>(W1, w1c);
    convw_kernel<HH/BK, DD/BN><<<EE*(HH/BK)*(DD/BN), 256>>>(W2, w2c);
    gemm_kernel<DD/BK, HH/BN, true ><<<dim3(HH/BN, EE*64), 512, SMEM_BYTES>>>(w1c, b1);
    gemm_kernel<HH/BK, DD/BN, false><<<dim3(DD/BN, EE*64), 512, SMEM_BYTES>>>(w2c, b2);
    combine_kernel<<<TT, 256>>>(out);
}

// round 17
// speedup vs baseline: 1.0677x; 1.0677x over previous
#include <cuda_runtime.h>
#include <cuda_fp16.h>
#include <math.h>
#include <stdint.h>

#define TT 8192          // tokens = B*S
#define DD 1024          // model dim
#define EE 8             // experts
#define HH 2048          // hidden
#define NROWS (TT*2)     // top-2 routing rows
#define PADROWS (NROWS + EE*128)     // expert-padded rows (17408)
#define MAXTILES (PADROWS/128)       // 136

// GEMM tile geometry
#define BM 128
#define BN 256
#define BK 32
#define KPAD 8                        // row pad (halves): stride 40 halves = 80B
#define AST (BK + KPAD)               // 40
#define A_TILE_HL (BM * AST)          // 5120 halves
#define B_TILE_HL (BN * AST)          // 10240 halves
#define A_TILE_BYTES (A_TILE_HL*2)    // 10240
#define B_TILE_BYTES (B_TILE_HL*2)    // 20480
#define STG_BYTES (A_TILE_BYTES + B_TILE_BYTES)   // 30720
#define NSTAGE 4
#define SMEM_BYTES (NSTAGE*STG_BYTES)             // 122880

// ---------------- scratch (static device globals; no allocations) ----------
__device__ int   g_tok_e[NROWS];
__device__ float g_tok_w[NROWS];
__device__ int   g_counts[EE];
__device__ int   g_off_p[EE+1];
__device__ int   g_cnt2[EE];
__device__ int   g_row2tok[PADROWS];
__device__ float g_roww[PADROWS];
__device__ int   g_pos[NROWS];
// A tiles: [tile][ktile][128 x 40 halves]
__device__ __align__(1024) __half g_Xg[(size_t)MAXTILES * (DD/BK) * A_TILE_HL];
__device__ __align__(1024) __half g_H [(size_t)MAXTILES * (HH/BK) * A_TILE_HL];
// B tiles: [e][kt][nt][256 x 40 halves]  (n-major, k-contiguous)
__device__ __align__(1024) __half g_W1c[(size_t)EE * (DD/BK) * (HH/BN) * B_TILE_HL];
__device__ __align__(1024) __half g_W2c[(size_t)EE * (HH/BK) * (DD/BN) * B_TILE_HL];
__device__ float g_Y[(size_t)PADROWS * DD];

// ---------------- helpers ---------------------------------------------------
__device__ __forceinline__ float gelu_f(float v){
    float z = 0.7978845608028654f * (v + 0.044715f * v * v * v);
    float t; asm("tanh.approx.f32 %0, %1;" : "=f"(t) : "f"(z));
    return 0.5f * v * (1.0f + t);
}
__device__ __forceinline__ void mma16(float* c, const unsigned* a, const unsigned* b){
    asm volatile(
        "mma.sync.aligned.m16n8k16.row.col.f32.f16.f16.f32 "
        "{%0,%1,%2,%3}, {%4,%5,%6,%7}, {%8,%9}, {%0,%1,%2,%3};"
        : "+f"(c[0]), "+f"(c[1]), "+f"(c[2]), "+f"(c[3])
        : "r"(a[0]), "r"(a[1]), "r"(a[2]), "r"(a[3]), "r"(b[0]), "r"(b[1]));
}
__device__ __forceinline__ void ldsm4(unsigned* r, unsigned addr){
    asm volatile("ldmatrix.sync.aligned.m8n8.x4.shared.b16 {%0,%1,%2,%3}, [%4];"
        : "=r"(r[0]), "=r"(r[1]), "=r"(r[2]), "=r"(r[3]) : "r"(addr));
}
__device__ __forceinline__ unsigned s2u(const void* p){
    unsigned a;
    asm("{ .reg .u64 t; cvta.to.shared.u64 t, %1; cvt.u32.u64 %0, t; }" : "=r"(a) : "l"(p));
    return a;
}
__device__ __forceinline__ void mbar_init(unsigned mbar, unsigned cnt){
    asm volatile("mbarrier.init.shared.b64 [%0], %1;" :: "r"(mbar), "r"(cnt) : "memory");
}
__device__ __forceinline__ void mbar_expect(unsigned mbar, unsigned bytes){
    asm volatile("mbarrier.arrive.expect_tx.shared.b64 _, [%0], %1;" :: "r"(mbar), "r"(bytes) : "memory");
}
__device__ __forceinline__ void mbar_arrive(unsigned mbar){
    asm volatile("mbarrier.arrive.shared.b64 _, [%0];" :: "r"(mbar) : "memory");
}
__device__ __forceinline__ void mbar_wait(unsigned mbar, unsigned parity){
    asm volatile(
        "{\n\t"
        ".reg .pred P;\n\t"
        "LAB_%=:\n\t"
        "mbarrier.try_wait.parity.acquire.cta.shared::cta.b64 P, [%0], %1, 0x989680;\n\t"
        "@!P bra LAB_%=;\n\t"
        "}"
        :: "r"(mbar), "r"(parity) : "memory");
}
__device__ __forceinline__ void bulk_g2s(unsigned dst, const void* src, unsigned bytes, unsigned mbar){
    asm volatile(
        "cp.async.bulk.shared::cluster.global.mbarrier::complete_tx::bytes [%0], [%1], %2, [%3];"
        :: "r"(dst), "l"(src), "r"(bytes), "r"(mbar) : "memory");
}

// ---------------- kernel 0: zero per-launch state ---------------------------
__global__ void init_kernel(){
    if (threadIdx.x < EE) g_counts[threadIdx.x] = 0;
}

// ---------------- kernel 1: gating + top-2 routing --------------------------
__global__ void gate_kernel(const float* __restrict__ x,
                            const float* __restrict__ Wg,
                            const float* __restrict__ bg){
    __shared__ float sWg[DD*EE];
    __shared__ int scnt[EE];
    const int tid = threadIdx.x;
    if (tid < EE) scnt[tid] = 0;
    for (int i = tid; i < DD*EE/4; i += 256)
        ((float4*)sWg)[i] = ((const float4*)Wg)[i];
    __syncthreads();

    const int warp = tid >> 5, lane = tid & 31;
    for (int i = 0; i < 8; ++i){
        const int t = blockIdx.x * 64 + i * 8 + warp;
        float acc[EE];
        #pragma unroll
        for (int e = 0; e < EE; ++e) acc[e] = 0.f;
        const float* xr = x + (size_t)t * DD;
        for (int j = 0; j < DD/32; ++j){
            const int d = j * 32 + lane;
            const float xv = xr[d];
            const float4* w4 = (const float4*)(sWg + d * EE);
            float4 wa = w4[0], wb = w4[1];
            acc[0] += xv*wa.x; acc[1] += xv*wa.y; acc[2] += xv*wa.z; acc[3] += xv*wa.w;
            acc[4] += xv*wb.x; acc[5] += xv*wb.y; acc[6] += xv*wb.z; acc[7] += xv*wb.w;
        }
        #pragma unroll
        for (int off = 16; off; off >>= 1){
            #pragma unroll
            for (int e = 0; e < EE; ++e)
                acc[e] += __shfl_xor_sync(0xffffffffu, acc[e], off);
        }
        if (lane == 0){
            float l[EE];
            #pragma unroll
            for (int e = 0; e < EE; ++e) l[e] = acc[e] + bg[e];
            int e0 = 0; float l0 = l[0];
            #pragma unroll
            for (int e = 1; e < EE; ++e) if (l[e] > l0){ l0 = l[e]; e0 = e; }
            int e1 = -1; float l1 = -1e30f;
            #pragma unroll
            for (int e = 0; e < EE; ++e) if (e != e0 && l[e] > l1){ l1 = l[e]; e1 = e; }
            const float w0 = 1.0f / (1.0f + __expf(l1 - l0));
            g_tok_e[2*t] = e0;  g_tok_e[2*t+1] = e1;
            g_tok_w[2*t] = w0;  g_tok_w[2*t+1] = 1.0f - w0;
            atomicAdd(&scnt[e0], 1); atomicAdd(&scnt[e1], 1);
        }
    }
    __syncthreads();
    if (tid < EE) atomicAdd(&g_counts[tid], scnt[tid]);
}

// ---------------- kernel 2: padded exclusive scan ----------------------------
__global__ void scan_kernel(){
    if (threadIdx.x == 0){
        int o = 0;
        #pragma unroll
        for (int e = 0; e < EE; ++e){
            g_off_p[e] = o;
            o += ((g_counts[e] + 127) >> 7) << 7;
        }
        g_off_p[EE] = o;
    }
    if (threadIdx.x < EE) g_cnt2[threadIdx.x] = 0;
}

// ---------------- kernel 3: scatter tokens into expert-grouped rows ---------
__global__ void scatter_kernel(){
    __shared__ int sc[EE], sbase[EE];
    const int tid = threadIdx.x;
    if (tid < EE) sc[tid] = 0;
    __syncthreads();
    const int t = blockIdx.x * 256 + tid;
    const int e0 = g_tok_e[2*t], e1 = g_tok_e[2*t+1];
    const int s0 = atomicAdd(&sc[e0], 1);
    const int s1 = atomicAdd(&sc[e1], 1);
    __syncthreads();
    if (tid < EE) sbase[tid] = atomicAdd(&g_cnt2[tid], sc[tid]);
    __syncthreads();
    const int r0 = g_off_p[e0] + sbase[e0] + s0;
    const int r1 = g_off_p[e1] + sbase[e1] + s1;
    g_row2tok[r0] = t; g_roww[r0] = g_tok_w[2*t];   g_pos[2*t]   = r0;
    g_row2tok[r1] = t; g_roww[r1] = g_tok_w[2*t+1]; g_pos[2*t+1] = r1;
}

// ---------------- kernel 4: mark padding rows --------------------------------
__global__ void padfill_kernel(){
    const int e = blockIdx.x;
    const int cnt = g_counts[e];
    const int pcnt = ((cnt + 127) >> 7) << 7;
    for (int i = cnt + threadIdx.x; i < pcnt; i += 128)
        g_row2tok[g_off_p[e] + i] = -1;
}

// ---------------- kernel 5: gather x into padded fp16 A tiles ---------------
__global__ void gather_kernel(const float* __restrict__ x){
    const int pr = blockIdx.x;
    if (pr >= g_off_p[EE]) return;
    const int tok = g_row2tok[pr];
    const int tile = pr >> 7, rl = pr & 127;
    const int j = threadIdx.x;                 // 0..255
    const int kt = j >> 3, kc = j & 7;         // ktile, 4-half chunk
    float4 v = make_float4(0.f, 0.f, 0.f, 0.f);
    if (tok >= 0) v = *(const float4*)(x + (size_t)tok * DD + kt * BK + kc * 4);
    __half2 h0 = __floats2half2_rn(v.x, v.y);
    __half2 h1 = __floats2half2_rn(v.z, v.w);
    __half* dt = g_Xg + ((size_t)tile * (DD/BK) + kt) * A_TILE_HL + rl * AST + kc * 4;
    *(__half2*)(dt)     = h0;
    *(__half2*)(dt + 2) = h1;
}

// ---------------- kernel 6: weights -> padded fp16 B tiles (n-major) --------
template<int KT, int NT>
__global__ void convw_kernel(const float* __restrict__ W, __half* __restrict__ dst){
    __shared__ float sw[32][257];
    const int t  = blockIdx.x;
    const int nt = t % NT;
    const int kt = (t / NT) % KT;
    const int e  = t / (NT * KT);
    const int ND = NT * BN;
    const float* src = W + (((size_t)e * KT + kt) * 32) * ND + nt * BN;
    for (int i = threadIdx.x; i < 32*64; i += 256){
        const int k = i >> 6, c = i & 63;
        const float4 v = *(const float4*)(src + (size_t)k * ND + c * 4);
        sw[k][c*4+0] = v.x; sw[k][c*4+1] = v.y; sw[k][c*4+2] = v.z; sw[k][c*4+3] = v.w;
    }
    __syncthreads();
    __half* dt = dst + (size_t)t * B_TILE_HL;
    for (int i = threadIdx.x; i < 2048; i += 256){
        const int n = i >> 3, kc = i & 7;
        __half2 h0 = __floats2half2_rn(sw[kc*4+0][n], sw[kc*4+1][n]);
        __half2 h1 = __floats2half2_rn(sw[kc*4+2][n], sw[kc*4+3][n]);
        __half* o = dt + n * AST + kc * 4;
        *(__half2*)(o)     = h0;
        *(__half2*)(o + 2) = h1;
    }
}

// ---------------- FP16 tensor-core grouped GEMM ------------------------------
// 8 compute warps (2x4, 64x64 tiles) + 1 producer warp (warp-specialized).
// FIRST=true : g_H tiles = fp16(gelu( g_Xg @ W1c + b1 )),  KT=32, NT=8
// FIRST=false: g_Y rows  =           g_H  @ W2c + b2,      KT=64, NT=4
template<int KT, int NT, bool FIRST>
__global__ __launch_bounds__(288, 1)
void gemm_kernel(const __half* __restrict__ Bw, const float* __restrict__ bias){
    extern __shared__ __half smh[];
    __shared__ __align__(8) unsigned long long s_bar[2*NSTAGE];

    const int e   = blockIdx.y >> 6;
    const int mt  = blockIdx.y & 63;
    const int cnt = g_counts[e];
    if (mt * BM >= cnt) return;
    const int tile = (g_off_p[e] >> 7) + mt;
    const int nt   = blockIdx.x;
    const int tid  = threadIdx.x;
    const int lane = tid & 31, wid = tid >> 5;

    const __half* Asrc = FIRST ? g_Xg : g_H;
    const unsigned sb    = s2u(smh);
    const unsigned FULLB = s2u(s_bar), EMPTYB = FULLB + 8*NSTAGE;

    if (tid == 0){
        #pragma unroll
        for (int s = 0; s < NSTAGE; ++s){ mbar_init(FULLB + 8*s, 1); mbar_init(EMPTYB + 8*s, 8); }
    }
    __syncthreads();

    if (wid == 8){
        // ---- producer warp: owns the whole copy loop ----
        if (lane == 0){
            for (int kt = 0; kt < KT; ++kt){
                const int s = kt & (NSTAGE-1);
                if (kt >= NSTAGE) mbar_wait(EMPTYB + 8*s, ((kt >> 2) - 1) & 1);
                mbar_expect(FULLB + 8*s, STG_BYTES);
                bulk_g2s(sb + s*STG_BYTES,
                         Asrc + ((size_t)tile*KT + kt)*A_TILE_HL, A_TILE_BYTES, FULLB + 8*s);
                bulk_g2s(sb + s*STG_BYTES + A_TILE_BYTES,
                         Bw + (((size_t)e*KT + kt)*NT + nt)*B_TILE_HL, B_TILE_BYTES, FULLB + 8*s);
            }
        }
        return;
    }

    // ---- compute warps 0..7: 2x4 grid, 64x64 warp tiles ----
    const int wm = wid >> 2, wn = wid & 3;

    float c[4][8][4];
    #pragma unroll
    for (int i = 0; i < 4; ++i)
        #pragma unroll
        for (int j = 0; j < 8; ++j)
            #pragma unroll
            for (int q = 0; q < 4; ++q) c[i][j][q] = 0.f;

    // ldmatrix lane addressing (half offsets within tiles, x4 form)
    const int aOff = (wm*64 + (lane & 15))*AST + (lane >> 4)*8;              // + am*16*AST + kk*16
    const int bOff = (wn*64 + (lane & 7) + ((lane >> 4) << 3))*AST + ((lane >> 3) & 1)*8;  // + bj*16*AST + kk*16

    for (int kt = 0; kt < KT; ++kt){
        const int s = kt & (NSTAGE-1);
        const unsigned ph = (kt >> 2) & 1;
        mbar_wait(FULLB + 8*s, ph);
        const unsigned As = sb + s*STG_BYTES;
        const unsigned Bs = As + A_TILE_BYTES;

        unsigned a[2][4][4], b[2][4][4];
        #pragma unroll
        for (int kk = 0; kk < 2; ++kk){
            #pragma unroll
            for (int am = 0; am < 4; ++am)
                ldsm4(a[kk][am], As + 2*(aOff + am*16*AST + kk*16));
            #pragma unroll
            for (int bj = 0; bj < 4; ++bj)
                ldsm4(b[kk][bj], Bs + 2*(bOff + bj*16*AST + kk*16));
        }
        __syncwarp();
        if (lane == 0) mbar_arrive(EMPTYB + 8*s);

        #pragma unroll
        for (int kk = 0; kk < 2; ++kk)
            #pragma unroll
            for (int am = 0; am < 4; ++am)
                #pragma unroll
                for (int bj = 0; bj < 4; ++bj){
                    mma16(c[am][2*bj  ], a[kk][am], &b[kk][bj][0]);
                    mma16(c[am][2*bj+1], a[kk][am], &b[kk][bj][2]);
                }
    }

    // ---- epilogue: +bias [, gelu], store ----
    const int ND = NT * BN;
    const int g = lane >> 2, tg = lane & 3;
    #pragma unroll
    for (int am = 0; am < 4; ++am){
        #pragma unroll
        for (int bn = 0; bn < 8; ++bn){
            const int lc = wn*64 + bn*8 + 2*tg;
            const int gc = nt*BN + lc;
            const float bb0 = bias[e*ND + gc];
            const float bb1 = bias[e*ND + gc + 1];
            #pragma unroll
            for (int h = 0; h < 2; ++h){
                const int r = wm*64 + am*16 + g + h*8;
                float v0 = c[am][bn][h*2+0] + bb0;
                float v1 = c[am][bn][h*2+1] + bb1;
                if (FIRST){
                    __half* dt = g_H + ((size_t)tile*(HH/BK) + (gc >> 5))*A_TILE_HL
                               + r*AST + (gc & 31);
                    *(__half2*)dt = __floats2half2_rn(gelu_f(v0), gelu_f(v1));
                } else {
                    float* dt = g_Y + ((size_t)(tile*BM + r))*DD + gc;
                    *(float2*)dt = make_float2(v0, v1);
                }
            }
        }
    }
}

// ---------------- kernel 9: weighted combine (no atomics) -------------------
__global__ void combine_kernel(float* __restrict__ out){
    const int t = blockIdx.x, i = threadIdx.x;
    const int r0 = g_pos[2*t], r1 = g_pos[2*t+1];
    const float w0 = g_roww[r0], w1 = g_roww[r1];
    const float4 a = ((const float4*)(g_Y + (size_t)r0 * DD))[i];
    const float4 b = ((const float4*)(g_Y + (size_t)r1 * DD))[i];
    float4 r;
    r.x = w0*a.x + w1*b.x; r.y = w0*a.y + w1*b.y;
    r.z = w0*a.z + w1*b.z; r.w = w0*a.w + w1*b.w;
    ((float4*)(out + (size_t)t * DD))[i] = r;
}

// ---------------- launch -----------------------------------------------------
extern "C" void kernel_launch(void* const* d_in, const int* in_sizes, int n_in,
                              void* d_out, int out_size){
    // input order: x, top_k(scalar), Wg, bg, W1, b1, W2, b2 (robust to dropped scalar)
    const int sh = (n_in >= 8) ? 0 : -1;
    const float* x  = (const float*)d_in[0];
    const float* Wg = (const float*)d_in[2 + sh];
    const float* bg = (const float*)d_in[3 + sh];
    const float* W1 = (const float*)d_in[4 + sh];
    const float* b1 = (const float*)d_in[5 + sh];
    const float* W2 = (const float*)d_in[6 + sh];
    const float* b2 = (const float*)d_in[7 + sh];
    float* out = (float*)d_out;

    __half* w1c; cudaGetSymbolAddress((void**)&w1c, g_W1c);
    __half* w2c; cudaGetSymbolAddress((void**)&w2c, g_W2c);

    cudaFuncSetAttribute(gemm_kernel<DD/BK, HH/BN, true >,
                         cudaFuncAttributeMaxDynamicSharedMemorySize, SMEM_BYTES);
    cudaFuncSetAttribute(gemm_kernel<HH/BK, DD/BN, false>,
                         cudaFuncAttributeMaxDynamicSharedMemorySize, SMEM_BYTES);

    init_kernel<<<1, 32>>>();
    gate_kernel<<<128, 256>>>(x, Wg, bg);
    scan_kernel<<<1, 32>>>();
    scatter_kernel<<<TT/256, 256>>>();
    padfill_kernel<<<EE, 128>>>();
    gather_kernel<<<PADROWS, 256>>>(x);
    convw_kernel<DD/BK, HH/BN><<<EE*(DD/BK)*(HH/BN), 256>>>(W1, w1c);
    convw_kernel<HH/BK, DD/BN><<<EE*(HH/BK)*(DD/BN), 256>>>(W2, w2c);
    gemm_kernel<DD/BK, HH/BN, true ><<<dim3(HH/BN, EE*64), 288, SMEM_BYTES>>>(w1c, b1);
    gemm_kernel<HH/BK, DD/BN, false><<<dim3(DD/BN, EE*64), 288, SMEM_BYTES>>>(w2c, b2);
    combine_kernel<<<TT, 256>>>(out);
}